// round 16
// baseline (speedup 1.0000x reference)
#include <cuda_runtime.h>
#include <cuda.h>
#include <cstdint>

// Correlation layer: out[b, (dy+4)*9+(dx+4), y, x] =
//   (1/C) * sum_c first[b,c,y,x] * second[b,c,y+dy,x+dx]   (zero-padded)
// B=8, C=256, H=96, W=160, MAX_DISP=4 -> 81 displacements.
//
// R16 = R15 (TMA staging + R7 compute mapping, 150 us, scalar-FFMA roofline)
//       + mov-free FFMA2 on even displacements. The R8 spill confound
//       (cp.async staging registers) is gone with TMA staging.

#define MAXD    4
#define NDISP   9
#define BATCH   8
#define CHN     256
#define HH      96
#define WW      160
#define HW      (HH*WW)

#define TY      4
#define TX      32
#define PX      8
#define CH      8
#define NITER   (CHN/CH)       // 32

#define BROWS   (TY + 2*MAXD)  // 12
#define BSTR    44             // B row stride = TMA box0 (4 pad cols, never read)
#define ASTR    36             // A row stride = TMA box0
#define BTILEP  (BROWS*BSTR)   // 528 floats per channel
#define ATILEP  (TY*ASTR)      // 144 floats per channel
#define BUF_FLOATS (CH*(BTILEP+ATILEP))   // 5376 floats
#define BUF_BYTES  (BUF_FLOATS*4)         // 21504 B (TMA tx per chunk)
#define MBAR_REGION 128
#define SMEM_BYTES (MBAR_REGION + 2*BUF_BYTES)   // 43136 B

#define NTHREADS 144           // 4 xg * 4 yy * 9 w

__device__ __forceinline__ uint32_t smem_u32(const void* p) {
    return (uint32_t)__cvta_generic_to_shared(p);
}
__device__ __forceinline__ void mbar_init(uint32_t addr, uint32_t count) {
    asm volatile("mbarrier.init.shared::cta.b64 [%0], %1;"
                 :: "r"(addr), "r"(count) : "memory");
}
__device__ __forceinline__ void mbar_expect_tx(uint32_t addr, uint32_t bytes) {
    asm volatile("mbarrier.arrive.expect_tx.shared::cta.b64 _, [%0], %1;"
                 :: "r"(addr), "r"(bytes) : "memory");
}
__device__ __forceinline__ void mbar_wait(uint32_t addr, uint32_t parity) {
    asm volatile(
        "{\n\t.reg .pred P;\n\t"
        "W%=:\n\t"
        "mbarrier.try_wait.parity.shared::cta.b64 P, [%0], %1;\n\t"
        "@!P bra W%=;\n\t}"
        :: "r"(addr), "r"(parity) : "memory");
}
__device__ __forceinline__ void tma3d(uint32_t dst, const CUtensorMap* map,
                                      int x, int y, int z, uint32_t mbar) {
    asm volatile(
        "cp.async.bulk.tensor.3d.shared::cta.global.tile.mbarrier::complete_tx::bytes "
        "[%0], [%1, {%2, %3, %4}], [%5];"
        :: "r"(dst), "l"(map), "r"(x), "r"(y), "r"(z), "r"(mbar) : "memory");
}
__device__ __forceinline__ void fence_async() {
    asm volatile("fence.proxy.async.shared::cta;" ::: "memory");
}

// ---- packed f32x2 helpers ----
typedef unsigned long long u64;
__device__ __forceinline__ u64 pack2(float lo, float hi) {
    u64 r;
    asm("mov.b64 %0, {%1, %2};" : "=l"(r) : "f"(lo), "f"(hi));
    return r;
}
__device__ __forceinline__ void ffma2(u64& d, u64 a, u64 b) {
    asm("fma.rn.f32x2 %0, %1, %2, %0;" : "+l"(d) : "l"(a), "l"(b));
}
__device__ __forceinline__ void unpack2(float& lo, float& hi, u64 v) {
    asm("mov.b64 {%0, %1}, %2;" : "=f"(lo), "=f"(hi) : "l"(v));
}

extern __shared__ float smem[];

__global__ __launch_bounds__(NTHREADS, 3)
void corr_kernel(const __grid_constant__ CUtensorMap tmA,
                 const __grid_constant__ CUtensorMap tmB,
                 float* __restrict__ out)
{
    const uint32_t smem0 = smem_u32(smem);     // mbar[0] @ +0, mbar[1] @ +8
    float* bufs = smem + MBAR_REGION / 4;
    const uint32_t bufs0 = smem0 + MBAR_REGION;

    const int xt  = blockIdx.x * TX;
    const int y0  = blockIdx.y * TY;
    const int b   = blockIdx.z;
    const int tid = threadIdx.x;
    const int zb  = b * CHN;

    if (tid == 0) {
        mbar_init(smem0 + 0, 1);
        mbar_init(smem0 + 8, 1);
        fence_async();
    }
    __syncthreads();

    // ---- prologue: stage chunks 0 and 1 ----
    if (tid == 0) {
        mbar_expect_tx(smem0 + 0, BUF_BYTES);
        tma3d(bufs0,                   &tmB, xt - MAXD, y0 - MAXD, zb,      smem0 + 0);
        tma3d(bufs0 + CH * BTILEP * 4, &tmA, xt,        y0,        zb,      smem0 + 0);
        mbar_expect_tx(smem0 + 8, BUF_BYTES);
        tma3d(bufs0 + BUF_BYTES,                   &tmB, xt - MAXD, y0 - MAXD, zb + CH, smem0 + 8);
        tma3d(bufs0 + BUF_BYTES + CH * BTILEP * 4, &tmA, xt,        y0,        zb + CH, smem0 + 8);
    }

    // ---- compute-role mapping (R7, measured-good) ----
    const int xg = tid & 3;           // 8-pixel x-strip
    const int yy = (tid >> 2) & 3;    // row within tile
    const int w  = tid >> 4;          // dy index 0..8 (two per warp -> broadcast)

    // even j packed over pixel pairs; odd j scalar
    u64   acc2[4][5];                 // [pixel-pair][j/2], j in {0,2,4,6,8}
    float acco[PX][4];                // [pixel][(j-1)/2], j in {1,3,5,7}
    #pragma unroll
    for (int i = 0; i < 4; ++i)
        #pragma unroll
        for (int j = 0; j < 5; ++j)
            acc2[i][j] = 0ull;
    #pragma unroll
    for (int i = 0; i < PX; ++i)
        #pragma unroll
        for (int j = 0; j < 4; ++j)
            acco[i][j] = 0.0f;

    int ph0 = 0, ph1 = 0;
    #pragma unroll 1
    for (int it = 0; it < NITER; ++it) {
        const int buf = it & 1;
        if (buf == 0) { mbar_wait(smem0 + 0, ph0); ph0 ^= 1; }
        else          { mbar_wait(smem0 + 8, ph1); ph1 ^= 1; }

        const float* Bb = bufs + buf * BUF_FLOATS;
        const float* Ab = Bb + CH * BTILEP;
        #pragma unroll
        for (int cc = 0; cc < CH; ++cc) {
            const float* arow = &Ab[cc * ATILEP + yy * ASTR + 8 * xg];
            const float4 a0 = *reinterpret_cast<const float4*>(arow);
            const float4 a1 = *reinterpret_cast<const float4*>(arow + 4);

            // Pixel p = 8*xg+i uses halo cols 8*xg .. 8*xg+15 of row yy+w
            const float* brow = &Bb[cc * BTILEP + (yy + w) * BSTR + 8 * xg];
            const float4 b0 = *reinterpret_cast<const float4*>(brow);
            const float4 b1 = *reinterpret_cast<const float4*>(brow + 4);
            const float4 b2 = *reinterpret_cast<const float4*>(brow + 8);
            const float4 b3 = *reinterpret_cast<const float4*>(brow + 12);

            // Natural aligned pairs straight from the LDS.128 quads (mov-free)
            const u64 ap[4] = { pack2(a0.x, a0.y), pack2(a0.z, a0.w),
                                pack2(a1.x, a1.y), pack2(a1.z, a1.w) };
            const u64 bp[8] = { pack2(b0.x, b0.y), pack2(b0.z, b0.w),
                                pack2(b1.x, b1.y), pack2(b1.z, b1.w),
                                pack2(b2.x, b2.y), pack2(b2.z, b2.w),
                                pack2(b3.x, b3.y), pack2(b3.z, b3.w) };

            // even j = 2*jp: acc2[i2][jp] += ap[i2] * bp[i2+jp]   (20 FFMA2)
            #pragma unroll
            for (int i2 = 0; i2 < 4; ++i2)
                #pragma unroll
                for (int jp = 0; jp < 5; ++jp)
                    ffma2(acc2[i2][jp], ap[i2], bp[i2 + jp]);

            // odd j: scalar FFMA (32)
            const float a[PX]  = {a0.x, a0.y, a0.z, a0.w,
                                  a1.x, a1.y, a1.z, a1.w};
            const float bv[16] = {b0.x, b0.y, b0.z, b0.w,
                                  b1.x, b1.y, b1.z, b1.w,
                                  b2.x, b2.y, b2.z, b2.w,
                                  b3.x, b3.y, b3.z, b3.w};
            #pragma unroll
            for (int i = 0; i < PX; ++i)
                #pragma unroll
                for (int jo = 0; jo < 4; ++jo)
                    acco[i][jo] = fmaf(a[i], bv[i + 2 * jo + 1], acco[i][jo]);
        }

        __syncthreads();              // all threads done reading this buffer
        if (it + 2 < NITER && tid == 0) {
            fence_async();
            const uint32_t mb  = smem0 + 8u * (uint32_t)buf;
            const uint32_t dst = bufs0 + (uint32_t)buf * BUF_BYTES;
            const int z = zb + (it + 2) * CH;
            mbar_expect_tx(mb, BUF_BYTES);
            tma3d(dst,                   &tmB, xt - MAXD, y0 - MAXD, z, mb);
            tma3d(dst + CH * BTILEP * 4, &tmA, xt,        y0,        z, mb);
        }
    }

    // ---- epilogue: mean over C, float4-pair stores ----
    const float scale = 1.0f / (float)CHN;
    const int y = y0 + yy;
    const int x = xt + 8 * xg;
    #pragma unroll
    for (int j = 0; j < NDISP; ++j) {
        const int d = w * NDISP + j;
        float* orow = &out[(((size_t)b * 81 + d) * HH + y) * WW + x];
        float p[PX];
        if ((j & 1) == 0) {
            #pragma unroll
            for (int i2 = 0; i2 < 4; ++i2)
                unpack2(p[2 * i2], p[2 * i2 + 1], acc2[i2][j >> 1]);
        } else {
            #pragma unroll
            for (int i = 0; i < PX; ++i)
                p[i] = acco[i][(j - 1) >> 1];
        }
        float4 o0, o1;
        o0.x = p[0] * scale; o0.y = p[1] * scale;
        o0.z = p[2] * scale; o0.w = p[3] * scale;
        o1.x = p[4] * scale; o1.y = p[5] * scale;
        o1.z = p[6] * scale; o1.w = p[7] * scale;
        *reinterpret_cast<float4*>(orow)     = o0;
        *reinterpret_cast<float4*>(orow + 4) = o1;
    }
}

// ---- host side ----

typedef CUresult (*PFN_encodeTiled)(
    CUtensorMap*, CUtensorMapDataType, cuuint32_t, void*,
    const cuuint64_t*, const cuuint64_t*, const cuuint32_t*, const cuuint32_t*,
    CUtensorMapInterleave, CUtensorMapSwizzle, CUtensorMapL2promotion,
    CUtensorMapFloatOOBfill);

extern "C" void kernel_launch(void* const* d_in, const int* in_sizes, int n_in,
                              void* d_out, int out_size)
{
    float* first  = (float*)d_in[0];
    float* second = (float*)d_in[1];
    float* out    = (float*)d_out;

    PFN_encodeTiled encode = nullptr;
    cudaDriverEntryPointQueryResult qr;
    cudaGetDriverEntryPointByVersion("cuTensorMapEncodeTiled",
                                     (void**)&encode, 12000,
                                     cudaEnableDefault, &qr);
    if (!encode) return;

    cuuint64_t dims[3]    = {WW, HH, (cuuint64_t)CHN * BATCH};
    cuuint64_t strides[2] = {(cuuint64_t)WW * 4, (cuuint64_t)HW * 4};
    cuuint32_t elemstr[3] = {1, 1, 1};
    cuuint32_t boxA[3] = {ASTR, TY,    CH};   // 36 x 4 x 8
    cuuint32_t boxB[3] = {BSTR, BROWS, CH};   // 44 x 12 x 8

    CUtensorMap tmA, tmB;
    encode(&tmA, CU_TENSOR_MAP_DATA_TYPE_FLOAT32, 3, (void*)first,
           dims, strides, boxA, elemstr,
           CU_TENSOR_MAP_INTERLEAVE_NONE, CU_TENSOR_MAP_SWIZZLE_NONE,
           CU_TENSOR_MAP_L2_PROMOTION_L2_128B, CU_TENSOR_MAP_FLOAT_OOB_FILL_NONE);
    encode(&tmB, CU_TENSOR_MAP_DATA_TYPE_FLOAT32, 3, (void*)second,
           dims, strides, boxB, elemstr,
           CU_TENSOR_MAP_INTERLEAVE_NONE, CU_TENSOR_MAP_SWIZZLE_NONE,
           CU_TENSOR_MAP_L2_PROMOTION_L2_128B, CU_TENSOR_MAP_FLOAT_OOB_FILL_NONE);

    // Idempotent, deterministic, not stream-ordered (capture-safe).
    cudaFuncSetAttribute(corr_kernel,
                         cudaFuncAttributeMaxDynamicSharedMemorySize, SMEM_BYTES);
    cudaFuncSetAttribute(corr_kernel,
                         cudaFuncAttributePreferredSharedMemoryCarveout, 100);

    dim3 grid(WW / TX, HH / TY, BATCH);   // (5, 24, 8)
    dim3 block(NTHREADS);
    corr_kernel<<<grid, block, SMEM_BYTES>>>(tmA, tmB, out);
}